// round 2
// baseline (speedup 1.0000x reference)
#include <cuda_runtime.h>

#define B_ 4
#define C_ 256
#define N_ 4096

// scratch: normalized-x (Q/K) and conv output (V), both [B][N][C]
__device__ float g_q[(size_t)B_ * N_ * C_];
__device__ float g_v[(size_t)B_ * N_ * C_];

// ---------------------------------------------------------------------------
// Kernel 1: per-pixel channel L2 norm + transpose  x[B,C,N] -> g_q[B,N,C]
// block = (b, 32-pixel tile), 256 threads
// ---------------------------------------------------------------------------
__global__ __launch_bounds__(256) void k_normxpose(const float* __restrict__ x) {
    __shared__ float tile[C_ * 33];   // [c][n] padded
    __shared__ float red[8 * 32];
    __shared__ float rn[32];

    int b  = blockIdx.x >> 7;             // 128 n-tiles per batch
    int n0 = (blockIdx.x & 127) * 32;
    int t  = threadIdx.x;
    int nl = t & 31;
    int cg = t >> 5;                       // 0..7

    const float* xb = x + (size_t)b * C_ * N_;

#pragma unroll 8
    for (int p = 0; p < 32; ++p) {
        int c = cg + p * 8;
        tile[c * 33 + nl] = xb[(size_t)c * N_ + n0 + nl];
    }
    __syncthreads();

    float ss = 0.f;
#pragma unroll 8
    for (int c = cg; c < C_; c += 8) {
        float v = tile[c * 33 + nl];
        ss += v * v;
    }
    red[cg * 32 + nl] = ss;
    __syncthreads();

    if (t < 32) {
        float s = 0.f;
#pragma unroll
        for (int g = 0; g < 8; ++g) s += red[g * 32 + t];
        rn[t] = 1.f / fmaxf(sqrtf(s), 1e-8f);
    }
    __syncthreads();

    float* qb = g_q + (size_t)b * N_ * C_;
#pragma unroll 8
    for (int n = 0; n < 32; ++n) {
        qb[(size_t)(n0 + n) * C_ + t] = tile[t * 33 + n] * rn[n];
    }
}

// ---------------------------------------------------------------------------
// Kernel 2: 1x1 conv  g_v[b][n][o] = sum_c W[o][c] * x[b][c][n] + bias[o]
// block = 64n x 64o tile, 256 threads, 4x4 micro-tile
// ---------------------------------------------------------------------------
__global__ __launch_bounds__(256) void k_conv1x1(const float* __restrict__ x,
                                                 const float* __restrict__ Wm,
                                                 const float* __restrict__ bias) {
    __shared__ float xs[16 * 68];   // [kc][n]
    __shared__ float ws[16 * 68];   // [kc][o]

    int n0 = blockIdx.x * 64;
    int o0 = blockIdx.y * 64;
    int b  = blockIdx.z;
    int t  = threadIdx.x;
    int tx = t & 15, ty = t >> 4;

    const float* xb = x + (size_t)b * C_ * N_;

    float acc[4][4];
#pragma unroll
    for (int r = 0; r < 4; ++r)
#pragma unroll
        for (int c = 0; c < 4; ++c) acc[r][c] = 0.f;

    for (int kc = 0; kc < C_; kc += 16) {
        __syncthreads();
#pragma unroll
        for (int p = 0; p < 4; ++p) {
            int idx = t + p * 256;
            int kk = idx >> 6, nl = idx & 63;
            xs[kk * 68 + nl] = xb[(size_t)(kc + kk) * N_ + n0 + nl];
        }
#pragma unroll
        for (int p = 0; p < 4; ++p) {
            int idx = t + p * 256;
            int ol = idx >> 4, kk = idx & 15;
            ws[kk * 68 + ol] = Wm[(size_t)(o0 + ol) * C_ + kc + kk];
        }
        __syncthreads();

#pragma unroll
        for (int kk = 0; kk < 16; ++kk) {
            float xv[4], wv[4];
#pragma unroll
            for (int r = 0; r < 4; ++r) xv[r] = xs[kk * 68 + ty * 4 + r];
#pragma unroll
            for (int c = 0; c < 4; ++c) wv[c] = ws[kk * 68 + tx * 4 + c];
#pragma unroll
            for (int r = 0; r < 4; ++r)
#pragma unroll
                for (int c = 0; c < 4; ++c) acc[r][c] += xv[r] * wv[c];
        }
    }

    float bv[4];
#pragma unroll
    for (int c = 0; c < 4; ++c) bv[c] = bias[o0 + tx * 4 + c];

    float* vb = g_v + (size_t)b * N_ * C_;
#pragma unroll
    for (int r = 0; r < 4; ++r) {
        float4 o;
        o.x = acc[r][0] + bv[0];
        o.y = acc[r][1] + bv[1];
        o.z = acc[r][2] + bv[2];
        o.w = acc[r][3] + bv[3];
        *reinterpret_cast<float4*>(&vb[(size_t)(n0 + ty * 4 + r) * C_ + o0 + tx * 4]) = o;
    }
}

// ---------------------------------------------------------------------------
// Kernel 3: fused  out[b,c,n] = sum_m relu(q_n . q_m)^2 * v[m][c]
// block = (64-query tile, batch), 256 threads (16x16)
// Q tile resident in smem; loop key tiles: S = Q K^T, P = relu(S)^2, O += P V
// ---------------------------------------------------------------------------
#define QS_STRIDE 260   // 256 + 4 pad
#define KS_STRIDE 68    // 64  + 4 pad   Ks[kk][j]
#define PS_STRIDE 68    // 64  + 4 pad   Ps[i][j]
#define VS_STRIDE 260   // 256 + 4 pad   Vs[mm][c]

__global__ __launch_bounds__(256, 2) void k_ppm_attn(float* __restrict__ out) {
    extern __shared__ float sm[];
    float* Qs = sm;                         // 64 * 260
    float* Ks = Qs + 64 * QS_STRIDE;        // 32 * 68
    float* Ps = Ks + 32 * KS_STRIDE;        // 64 * 68
    float* Vs = Ps + 64 * PS_STRIDE;        // 16 * 260

    int n0 = blockIdx.x * 64;
    int b  = blockIdx.y;
    int t  = threadIdx.x;
    int tx = t & 15, ty = t >> 4;

    const float* qb = g_q + (size_t)b * N_ * C_;
    const float* vb = g_v + (size_t)b * N_ * C_;

    // load Q tile [64 x 256]
#pragma unroll 4
    for (int p = 0; p < 64; ++p) {
        int idx = t + p * 256;
        int row = idx >> 8, col = idx & 255;
        Qs[row * QS_STRIDE + col] = qb[(size_t)(n0 + row) * C_ + col];
    }

    // O accumulators: rows i = ty*4 + r ; cols j = q*64 + tx*4 + cc
    float O[4][4][4];
#pragma unroll
    for (int r = 0; r < 4; ++r)
#pragma unroll
        for (int q = 0; q < 4; ++q)
#pragma unroll
            for (int cc = 0; cc < 4; ++cc) O[r][q][cc] = 0.f;

    for (int mt = 0; mt < N_ / 64; ++mt) {
        int m0 = mt * 64;

        // ---- S = Q K^T  (S[i][j] = sum_c q[n0+i][c] q[m0+j][c]) ----
        float S[4][4];
#pragma unroll
        for (int r = 0; r < 4; ++r)
#pragma unroll
            for (int c = 0; c < 4; ++c) S[r][c] = 0.f;

        for (int kc = 0; kc < C_; kc += 32) {
            __syncthreads();   // previous Ks readers done
#pragma unroll
            for (int p = 0; p < 8; ++p) {
                int idx = t + p * 256;
                int j = idx >> 5, kkl = idx & 31;
                Ks[kkl * KS_STRIDE + j] = qb[(size_t)(m0 + j) * C_ + kc + kkl];
            }
            __syncthreads();

#pragma unroll
            for (int kk = 0; kk < 32; ++kk) {
                float4 kvec = *reinterpret_cast<const float4*>(&Ks[kk * KS_STRIDE + tx * 4]);
                float qv[4];
#pragma unroll
                for (int r = 0; r < 4; ++r) qv[r] = Qs[(ty * 4 + r) * QS_STRIDE + kc + kk];
#pragma unroll
                for (int r = 0; r < 4; ++r) {
                    S[r][0] += qv[r] * kvec.x;
                    S[r][1] += qv[r] * kvec.y;
                    S[r][2] += qv[r] * kvec.z;
                    S[r][3] += qv[r] * kvec.w;
                }
            }
        }
        __syncthreads();

        // ---- P = relu(S)^2 into smem ----
#pragma unroll
        for (int r = 0; r < 4; ++r)
#pragma unroll
            for (int c = 0; c < 4; ++c) {
                float s = S[r][c];
                s = (s > 0.f) ? s * s : 0.f;
                Ps[(ty * 4 + r) * PS_STRIDE + tx * 4 + c] = s;
            }

        // ---- O += P V, streaming V in 16-row chunks ----
        for (int mc = 0; mc < 4; ++mc) {
            __syncthreads();   // previous Vs readers done; Ps writes visible after next sync
#pragma unroll
            for (int p = 0; p < 16; ++p) {
                int idx = t + p * 256;
                int row = idx >> 8, col = idx & 255;
                Vs[row * VS_STRIDE + col] = vb[(size_t)(m0 + mc * 16 + row) * C_ + col];
            }
            __syncthreads();

#pragma unroll
            for (int mm = 0; mm < 16; ++mm) {
                float pv[4];
#pragma unroll
                for (int r = 0; r < 4; ++r)
                    pv[r] = Ps[(ty * 4 + r) * PS_STRIDE + mc * 16 + mm];
                float4 vq[4];
#pragma unroll
                for (int q = 0; q < 4; ++q)
                    vq[q] = *reinterpret_cast<const float4*>(&Vs[mm * VS_STRIDE + q * 64 + tx * 4]);
#pragma unroll
                for (int r = 0; r < 4; ++r)
#pragma unroll
                    for (int q = 0; q < 4; ++q) {
                        O[r][q][0] += pv[r] * vq[q].x;
                        O[r][q][1] += pv[r] * vq[q].y;
                        O[r][q][2] += pv[r] * vq[q].z;
                        O[r][q][3] += pv[r] * vq[q].w;
                    }
            }
        }
    }

    __syncthreads();
    // transpose O through smem (reuse Qs buffer: 256 x 65 = 16640 floats)
    float* Os = Qs;
#pragma unroll
    for (int r = 0; r < 4; ++r)
#pragma unroll
        for (int q = 0; q < 4; ++q)
#pragma unroll
            for (int cc = 0; cc < 4; ++cc) {
                int i = ty * 4 + r;
                int j = q * 64 + tx * 4 + cc;
                Os[j * 65 + i] = O[r][q][cc];
            }
    __syncthreads();

    float* ob = out + (size_t)b * C_ * N_;
    int nl = t & 63, j0 = t >> 6;
#pragma unroll
    for (int j = j0; j < C_; j += 4) {
        ob[(size_t)j * N_ + n0 + nl] = Os[j * 65 + nl];
    }
}

// ---------------------------------------------------------------------------
extern "C" void kernel_launch(void* const* d_in, const int* in_sizes, int n_in,
                              void* d_out, int out_size) {
    const float* x    = (const float*)d_in[0];
    const float* Wm   = (const float*)d_in[1];
    const float* bias = (const float*)d_in[2];
    float* out = (float*)d_out;

    k_normxpose<<<B_ * (N_ / 32), 256>>>(x);
    k_conv1x1<<<dim3(N_ / 64, C_ / 64, B_), 256>>>(x, Wm, bias);

    size_t smem = (size_t)(64 * QS_STRIDE + 32 * KS_STRIDE + 64 * PS_STRIDE + 16 * VS_STRIDE) * sizeof(float);
    cudaFuncSetAttribute(k_ppm_attn, cudaFuncAttributeMaxDynamicSharedMemorySize, (int)smem);
    k_ppm_attn<<<dim3(N_ / 64, B_), 256, (int)smem>>>(out);
}

// round 5
// speedup vs baseline: 3.3582x; 3.3582x over previous
#include <cuda_runtime.h>
#include <cuda_bf16.h>
#include <cstdint>

#define B_ 4
#define C_ 256
#define N_ 4096

// ---------------- device scratch (split bf16 hi/lo) ----------------
__device__ __nv_bfloat16 g_qh[(size_t)B_*N_*C_];   // normalized x, [b][n][c]
__device__ __nv_bfloat16 g_ql[(size_t)B_*N_*C_];
__device__ __nv_bfloat16 g_xh[(size_t)B_*N_*C_];   // raw x transposed, [b][n][c]
__device__ __nv_bfloat16 g_xl[(size_t)B_*N_*C_];
__device__ __nv_bfloat16 g_wh[C_*C_];              // W, [o][c]
__device__ __nv_bfloat16 g_wl[C_*C_];
__device__ __nv_bfloat16 g_vh[(size_t)B_*C_*N_];   // conv out, [b][c][m]
__device__ __nv_bfloat16 g_vl[(size_t)B_*C_*N_];
__device__ __nv_bfloat16 g_ph[(size_t)B_*N_*N_];   // P = relu(sim)^2, [b][i][j]
__device__ __nv_bfloat16 g_pl[(size_t)B_*N_*N_];

// ---------------- helpers ----------------
__device__ __forceinline__ uint32_t smem_u32(const void* p) {
    uint32_t a;
    asm("{ .reg .u64 t; cvta.to.shared.u64 t, %1; cvt.u32.u64 %0, t; }" : "=r"(a) : "l"(p));
    return a;
}

#define CP16(dst, src) \
    asm volatile("cp.async.cg.shared.global [%0], [%1], 16;" :: "r"(dst), "l"(src))
#define CPCOMMIT() asm volatile("cp.async.commit_group;" ::: "memory")
#define CPWAIT1()  asm volatile("cp.async.wait_group 1;" ::: "memory")
#define CPWAIT0()  asm volatile("cp.async.wait_group 0;" ::: "memory")

#define LDSM_X4(r, ad) \
    asm volatile("ldmatrix.sync.aligned.m8n8.x4.shared.b16 {%0,%1,%2,%3}, [%4];" \
        : "=r"((r)[0]), "=r"((r)[1]), "=r"((r)[2]), "=r"((r)[3]) : "r"(ad))
#define LDSM_X2(r, ad) \
    asm volatile("ldmatrix.sync.aligned.m8n8.x2.shared.b16 {%0,%1}, [%2];" \
        : "=r"((r)[0]), "=r"((r)[1]) : "r"(ad))

#define MMA16816(d, a, bb) \
    asm volatile("mma.sync.aligned.m16n8k16.row.col.f32.bf16.bf16.f32 " \
        "{%0,%1,%2,%3}, {%4,%5,%6,%7}, {%8,%9}, {%0,%1,%2,%3};" \
        : "+f"((d)[0]), "+f"((d)[1]), "+f"((d)[2]), "+f"((d)[3]) \
        : "r"((a)[0]), "r"((a)[1]), "r"((a)[2]), "r"((a)[3]), "r"((bb)[0]), "r"((bb)[1]))

__device__ __forceinline__ void split2(float v, __nv_bfloat16& h, __nv_bfloat16& l) {
    h = __float2bfloat16(v);
    l = __float2bfloat16(v - __bfloat162float(h));
}

// swizzled 16B-chunk offset inside a [128 rows x 32 cols bf16] tile (64B rows)
__device__ __forceinline__ uint32_t swz(int row, int ch) {
    return (uint32_t)((row * 4 + (ch ^ ((row >> 1) & 3))) * 16);
}

// ---------------------------------------------------------------------------
// prep: per-pixel channel L2 norm; emit split(raw x) and split(normed x)
// in [b][n][c]. block = (b, 32-pixel tile), 256 threads
// ---------------------------------------------------------------------------
__global__ __launch_bounds__(256) void k_prep(const float* __restrict__ x) {
    __shared__ float tile[C_ * 33];
    __shared__ float red[8 * 32];
    __shared__ float rn[32];

    int b  = blockIdx.x >> 7;
    int n0 = (blockIdx.x & 127) * 32;
    int t  = threadIdx.x;
    int nl = t & 31;
    int cg = t >> 5;

    const float* xb = x + (size_t)b * C_ * N_;
#pragma unroll 8
    for (int p = 0; p < 32; ++p) {
        int c = cg + p * 8;
        tile[c * 33 + nl] = xb[(size_t)c * N_ + n0 + nl];
    }
    __syncthreads();

    float ss = 0.f;
#pragma unroll 8
    for (int c = cg; c < C_; c += 8) { float v = tile[c * 33 + nl]; ss += v * v; }
    red[cg * 32 + nl] = ss;
    __syncthreads();
    if (t < 32) {
        float s = 0.f;
#pragma unroll
        for (int g = 0; g < 8; ++g) s += red[g * 32 + t];
        rn[t] = 1.f / fmaxf(sqrtf(s), 1e-8f);
    }
    __syncthreads();

#pragma unroll 8
    for (int n = 0; n < 32; ++n) {
        size_t idx = (size_t)(b * N_ + n0 + n) * C_ + t;
        float xv = tile[t * 33 + n];
        __nv_bfloat16 h, l;
        split2(xv, h, l);          g_xh[idx] = h; g_xl[idx] = l;
        split2(xv * rn[n], h, l);  g_qh[idx] = h; g_ql[idx] = l;
    }
}

__global__ __launch_bounds__(256) void k_splitW(const float* __restrict__ W) {
    int i = blockIdx.x * 256 + threadIdx.x;
    __nv_bfloat16 h, l;
    split2(W[i], h, l);
    g_wh[i] = h; g_wl[i] = l;
}

// ---------------------------------------------------------------------------
// HMMA GEMM: D[128 x 128] = A[128,K] * B[128,K]^T, split-bf16 (3 MMAs/step)
// MODE 0: conv  A=x(m)  B=W(c)   +bias, split-store -> g_v[c][m]
// MODE 1: sim   A=q(n)  B=q(m)   relu^2, split-store -> g_p[m][n] AND g_p[n][m]
//               (triangular grid: blockIdx.y linear over bx<=by pairs)
// MODE 2: out   A=P(n)  B=v(c)   fp32 store -> out[c][n]
// ---------------------------------------------------------------------------
template<int MODE>
__global__ void __launch_bounds__(256, 1) k_gemm(const float* __restrict__ bias,
                                                 float* __restrict__ outf) {
    extern __shared__ __align__(128) char sm[];
    const uint32_t smb = smem_u32(sm);
    const int t = threadIdx.x;
    const int b = blockIdx.z;

    int bx, by;
    if (MODE == 1) {
        int id = blockIdx.x;                       // 0..527 over bx<=by
        int byy = (int)((sqrtf(8.f * id + 1.f) - 1.f) * 0.5f);
        // guard float rounding at triangular boundaries
        while ((byy + 1) * (byy + 2) / 2 <= id) ++byy;
        while (byy * (byy + 1) / 2 > id) --byy;
        by = byy; bx = id - byy * (byy + 1) / 2;   // bx <= by
    } else {
        bx = blockIdx.x; by = blockIdx.y;
    }

    constexpr int KTOT = (MODE == 2) ? N_ : C_;
    constexpr int KCH  = KTOT / 32;

    const __nv_bfloat16 *ah, *al, *bh, *bl;
    size_t a_rs, b_rs;
    if (MODE == 0) {
        size_t ao = (size_t)b * N_ * C_ + (size_t)bx * 128 * C_;
        ah = g_xh + ao; al = g_xl + ao; a_rs = C_;
        size_t bo = (size_t)by * 128 * C_;
        bh = g_wh + bo; bl = g_wl + bo; b_rs = C_;
    } else if (MODE == 1) {
        size_t ao = (size_t)b * N_ * C_ + (size_t)bx * 128 * C_;
        size_t bo = (size_t)b * N_ * C_ + (size_t)by * 128 * C_;
        ah = g_qh + ao; al = g_ql + ao; a_rs = C_;
        bh = g_qh + bo; bl = g_ql + bo; b_rs = C_;
    } else {
        size_t ao = (size_t)b * N_ * N_ + (size_t)bx * 128 * N_;
        size_t bo = (size_t)b * C_ * N_ + (size_t)by * 128 * N_;
        ah = g_ph + ao; al = g_pl + ao; a_rs = N_;
        bh = g_vh + bo; bl = g_vl + bo; b_rs = N_;
    }

    // stage s at smb + s*32768: Ah@0, Al@8192, Bh@16384, Bl@24576
    const int wid = t >> 5, lane = t & 31;
    const int wm = wid >> 2, wn = wid & 3;         // 2 x 4 warps
    const int m0w = wm * 64, n0w = wn * 32;

    float acc[4][4][4];
#pragma unroll
    for (int i = 0; i < 4; ++i)
#pragma unroll
        for (int j = 0; j < 4; ++j)
#pragma unroll
            for (int r = 0; r < 4; ++r) acc[i][j][r] = 0.f;

    // ---- prefetch helper (inlined twice) ----
#define PREFETCH(kc_) do {                                                     \
        int s_ = (kc_) & 1;                                                    \
        uint32_t st_ = smb + s_ * 32768;                                       \
        int k0_ = (kc_) * 32;                                                  \
        _Pragma("unroll")                                                      \
        for (int i_ = 0; i_ < 2; ++i_) {                                       \
            int lin_ = t + i_ * 256;                                           \
            int row_ = lin_ >> 2, ch_ = lin_ & 3;                              \
            uint32_t so_ = swz(row_, ch_);                                     \
            size_t ao_ = (size_t)row_ * a_rs + k0_ + ch_ * 8;                  \
            size_t bo_ = (size_t)row_ * b_rs + k0_ + ch_ * 8;                  \
            CP16(st_ + so_,          ah + ao_);                                \
            CP16(st_ + 8192 + so_,   al + ao_);                                \
            CP16(st_ + 16384 + so_,  bh + bo_);                                \
            CP16(st_ + 24576 + so_,  bl + bo_);                                \
        }                                                                      \
    } while (0)

    PREFETCH(0); CPCOMMIT();

    const int asub   = lane >> 3;                  // 0..3
    const int arow   = (asub & 1) * 8 + (lane & 7);
    const int achoff = asub >> 1;                  // 0..1
    const int bsub   = (lane >> 3) & 1;
    const int brow   = lane & 7;

#pragma unroll 1
    for (int kc = 0; kc < KCH; ++kc) {
        if (kc + 1 < KCH) { PREFETCH(kc + 1); CPCOMMIT(); CPWAIT1(); }
        else              { CPWAIT0(); }
        __syncthreads();

        uint32_t st = smb + (kc & 1) * 32768;
#pragma unroll
        for (int ks = 0; ks < 2; ++ks) {
            uint32_t Ah[4][4], Al[4][4], Bh[4][2], Bl[4][2];
#pragma unroll
            for (int i = 0; i < 4; ++i) {
                int row = m0w + i * 16 + arow;
                uint32_t ad = st + swz(row, ks * 2 + achoff);
                LDSM_X4(Ah[i], ad);
                LDSM_X4(Al[i], ad + 8192);
            }
#pragma unroll
            for (int j = 0; j < 4; ++j) {
                int row = n0w + j * 8 + brow;
                uint32_t ad = st + 16384 + swz(row, ks * 2 + bsub);
                LDSM_X2(Bh[j], ad);
                LDSM_X2(Bl[j], ad + 8192);
            }
#pragma unroll
            for (int i = 0; i < 4; ++i)
#pragma unroll
                for (int j = 0; j < 4; ++j) {
                    MMA16816(acc[i][j], Ah[i], Bh[j]);
                    MMA16816(acc[i][j], Ah[i], Bl[j]);
                    MMA16816(acc[i][j], Al[i], Bh[j]);
                }
        }
        __syncthreads();
    }
#undef PREFETCH

    // ---- epilogue: regs -> smem D[128][129] -> transformed stores ----
    float* Ds = (float*)sm;
#pragma unroll
    for (int i = 0; i < 4; ++i) {
        int r0 = m0w + i * 16 + (lane >> 2);
#pragma unroll
        for (int j = 0; j < 4; ++j) {
            int c0 = n0w + j * 8 + (lane & 3) * 2;
            Ds[r0 * 129 + c0]           = acc[i][j][0];
            Ds[r0 * 129 + c0 + 1]       = acc[i][j][1];
            Ds[(r0 + 8) * 129 + c0]     = acc[i][j][2];
            Ds[(r0 + 8) * 129 + c0 + 1] = acc[i][j][3];
        }
    }
    __syncthreads();

    const int jj = t & 127, half = t >> 7;
    float bv = 0.f;
    if (MODE == 0) bv = bias[by * 128 + jj];

    // pass 1: column reads (D^T) -> row index of output = D column jj
#pragma unroll 1
    for (int rb = 0; rb < 8; ++rb) {
        int r0 = half * 64 + rb * 8;
        float v[8];
#pragma unroll
        for (int u = 0; u < 8; ++u) v[u] = Ds[(r0 + u) * 129 + jj];

        if (MODE == 2) {
            float4* dst = (float4*)(outf + (size_t)b * C_ * N_
                                    + (size_t)(by * 128 + jj) * N_ + bx * 128 + r0);
            dst[0] = make_float4(v[0], v[1], v[2], v[3]);
            dst[1] = make_float4(v[4], v[5], v[6], v[7]);
        } else {
            __align__(16) __nv_bfloat16 hb[8], lb[8];
#pragma unroll
            for (int u = 0; u < 8; ++u) {
                float xv = v[u];
                if (MODE == 0) xv += bv;
                if (MODE == 1) { xv = fmaxf(xv, 0.f); xv = xv * xv; }
                split2(xv, hb[u], lb[u]);
            }
            size_t off;
            if (MODE == 0)
                off = (size_t)b * C_ * N_ + (size_t)(by * 128 + jj) * N_ + bx * 128 + r0;
            else
                off = (size_t)b * N_ * N_ + (size_t)(by * 128 + jj) * N_ + bx * 128 + r0;
            if (MODE == 0) {
                *(uint4*)(g_vh + off) = *(uint4*)hb;
                *(uint4*)(g_vl + off) = *(uint4*)lb;
            } else {
                *(uint4*)(g_ph + off) = *(uint4*)hb;
                *(uint4*)(g_pl + off) = *(uint4*)lb;
            }
        }
    }

    // pass 2 (MODE 1 only, off-diagonal tiles): row reads -> mirror block P[n][m]
    if (MODE == 1 && bx != by) {
        const int rr = t & 127, jh = t >> 7;
#pragma unroll 1
        for (int cb = 0; cb < 8; ++cb) {
            int c0 = jh * 64 + cb * 8;
            __align__(16) __nv_bfloat16 hb[8], lb[8];
#pragma unroll
            for (int u = 0; u < 8; ++u) {
                float xv = Ds[rr * 129 + c0 + u];
                xv = fmaxf(xv, 0.f); xv = xv * xv;
                split2(xv, hb[u], lb[u]);
            }
            size_t off = (size_t)b * N_ * N_
                       + (size_t)(bx * 128 + rr) * N_ + by * 128 + c0;
            *(uint4*)(g_ph + off) = *(uint4*)hb;
            *(uint4*)(g_pl + off) = *(uint4*)lb;
        }
    }
}

// ---------------------------------------------------------------------------
extern "C" void kernel_launch(void* const* d_in, const int* in_sizes, int n_in,
                              void* d_out, int out_size) {
    const float* x    = (const float*)d_in[0];
    const float* Wm   = (const float*)d_in[1];
    const float* bias = (const float*)d_in[2];
    float* out = (float*)d_out;

    const int SMEM = 128 * 129 * 4;   // 66048 >= 2*32768 stages
    cudaFuncSetAttribute(k_gemm<0>, cudaFuncAttributeMaxDynamicSharedMemorySize, SMEM);
    cudaFuncSetAttribute(k_gemm<1>, cudaFuncAttributeMaxDynamicSharedMemorySize, SMEM);
    cudaFuncSetAttribute(k_gemm<2>, cudaFuncAttributeMaxDynamicSharedMemorySize, SMEM);

    k_prep<<<B_ * (N_ / 32), 256>>>(x);
    k_splitW<<<C_ * C_ / 256, 256>>>(Wm);

    k_gemm<0><<<dim3(N_ / 128, C_ / 128, B_), 256, SMEM>>>(bias, nullptr);

    int tri = (N_ / 128) * (N_ / 128 + 1) / 2;     // 528 triangular tiles
    k_gemm<1><<<dim3(tri, 1, B_), 256, SMEM>>>(nullptr, nullptr);

    k_gemm<2><<<dim3(N_ / 128, C_ / 128, B_), 256, SMEM>>>(nullptr, out);
}

// round 6
// speedup vs baseline: 3.9449x; 1.1747x over previous
#include <cuda_runtime.h>
#include <cuda_bf16.h>
#include <cuda_fp16.h>
#include <cstdint>

#define B_ 4
#define C_ 256
#define N_ 4096

// ---------------- device scratch ----------------
__device__ __nv_bfloat16 g_qh[(size_t)B_*N_*C_];   // normalized x, [b][n][c] (bf16 split)
__device__ __nv_bfloat16 g_ql[(size_t)B_*N_*C_];
__device__ __nv_bfloat16 g_xh[(size_t)B_*N_*C_];   // raw x transposed, [b][n][c] (bf16 split)
__device__ __nv_bfloat16 g_xl[(size_t)B_*N_*C_];
__device__ __nv_bfloat16 g_wh[C_*C_];              // W, [o][c] (bf16 split)
__device__ __nv_bfloat16 g_wl[C_*C_];
__device__ __half        g_v [(size_t)B_*C_*N_];   // conv out, [b][c][m] (fp16 single)
__device__ __half        g_ph[(size_t)B_*N_*N_];   // P = relu(sim)^2, [b][i][j] (fp16 split)
__device__ __half        g_pl[(size_t)B_*N_*N_];

// ---------------- helpers ----------------
__device__ __forceinline__ uint32_t smem_u32(const void* p) {
    uint32_t a;
    asm("{ .reg .u64 t; cvta.to.shared.u64 t, %1; cvt.u32.u64 %0, t; }" : "=r"(a) : "l"(p));
    return a;
}

#define CP16(dst, src) \
    asm volatile("cp.async.cg.shared.global [%0], [%1], 16;" :: "r"(dst), "l"(src))
#define CPCOMMIT() asm volatile("cp.async.commit_group;" ::: "memory")
#define CPWAIT1()  asm volatile("cp.async.wait_group 1;" ::: "memory")
#define CPWAIT0()  asm volatile("cp.async.wait_group 0;" ::: "memory")

#define LDSM_X4(r, ad) \
    asm volatile("ldmatrix.sync.aligned.m8n8.x4.shared.b16 {%0,%1,%2,%3}, [%4];" \
        : "=r"((r)[0]), "=r"((r)[1]), "=r"((r)[2]), "=r"((r)[3]) : "r"(ad))
#define LDSM_X2(r, ad) \
    asm volatile("ldmatrix.sync.aligned.m8n8.x2.shared.b16 {%0,%1}, [%2];" \
        : "=r"((r)[0]), "=r"((r)[1]) : "r"(ad))

#define MMAB(d, a, bb) \
    asm volatile("mma.sync.aligned.m16n8k16.row.col.f32.bf16.bf16.f32 " \
        "{%0,%1,%2,%3}, {%4,%5,%6,%7}, {%8,%9}, {%0,%1,%2,%3};" \
        : "+f"((d)[0]), "+f"((d)[1]), "+f"((d)[2]), "+f"((d)[3]) \
        : "r"((a)[0]), "r"((a)[1]), "r"((a)[2]), "r"((a)[3]), "r"((bb)[0]), "r"((bb)[1]))
#define MMAH(d, a, bb) \
    asm volatile("mma.sync.aligned.m16n8k16.row.col.f32.f16.f16.f32 " \
        "{%0,%1,%2,%3}, {%4,%5,%6,%7}, {%8,%9}, {%0,%1,%2,%3};" \
        : "+f"((d)[0]), "+f"((d)[1]), "+f"((d)[2]), "+f"((d)[3]) \
        : "r"((a)[0]), "r"((a)[1]), "r"((a)[2]), "r"((a)[3]), "r"((bb)[0]), "r"((bb)[1]))

__device__ __forceinline__ void split2(float v, __nv_bfloat16& h, __nv_bfloat16& l) {
    h = __float2bfloat16(v);
    l = __float2bfloat16(v - __bfloat162float(h));
}
__device__ __forceinline__ void split2h(float v, __half& h, __half& l) {
    h = __float2half_rn(v);
    l = __float2half_rn(v - __half2float(h));
}

// swizzled 16B-chunk offset inside a [128 rows x 32 cols b16] tile (64B rows)
__device__ __forceinline__ uint32_t swz(int row, int ch) {
    return (uint32_t)((row * 4 + (ch ^ ((row >> 1) & 3))) * 16);
}

// ---------------------------------------------------------------------------
// prep: per-pixel channel L2 norm; emit split(raw x) and split(normed x)
// ---------------------------------------------------------------------------
__global__ __launch_bounds__(256) void k_prep(const float* __restrict__ x) {
    __shared__ float tile[C_ * 33];
    __shared__ float red[8 * 32];
    __shared__ float rn[32];

    int b  = blockIdx.x >> 7;
    int n0 = (blockIdx.x & 127) * 32;
    int t  = threadIdx.x;
    int nl = t & 31;
    int cg = t >> 5;

    const float* xb = x + (size_t)b * C_ * N_;
#pragma unroll 8
    for (int p = 0; p < 32; ++p) {
        int c = cg + p * 8;
        tile[c * 33 + nl] = xb[(size_t)c * N_ + n0 + nl];
    }
    __syncthreads();

    float ss = 0.f;
#pragma unroll 8
    for (int c = cg; c < C_; c += 8) { float v = tile[c * 33 + nl]; ss += v * v; }
    red[cg * 32 + nl] = ss;
    __syncthreads();
    if (t < 32) {
        float s = 0.f;
#pragma unroll
        for (int g = 0; g < 8; ++g) s += red[g * 32 + t];
        rn[t] = 1.f / fmaxf(sqrtf(s), 1e-8f);
    }
    __syncthreads();

#pragma unroll 8
    for (int n = 0; n < 32; ++n) {
        size_t idx = (size_t)(b * N_ + n0 + n) * C_ + t;
        float xv = tile[t * 33 + n];
        __nv_bfloat16 h, l;
        split2(xv, h, l);          g_xh[idx] = h; g_xl[idx] = l;
        split2(xv * rn[n], h, l);  g_qh[idx] = h; g_ql[idx] = l;
    }
}

__global__ __launch_bounds__(256) void k_splitW(const float* __restrict__ W) {
    int i = blockIdx.x * 256 + threadIdx.x;
    __nv_bfloat16 h, l;
    split2(W[i], h, l);
    g_wh[i] = h; g_wl[i] = l;
}

// ---------------------------------------------------------------------------
// HMMA GEMM: D[128 x 128] = A[128,K] * B[128,K]^T
// MODE 0: conv  bf16-split x bf16-split (3 MMA), +bias -> g_v[c][m] fp16
// MODE 1: sim   bf16-split x bf16-split (3 MMA), relu^2 -> g_p fp16-split,
//               mirror store (triangular grid over bx<=by)
// MODE 2: out   fp16-split(P) x fp16(V) (2 MMA) -> out[c][n] fp32
// 3-stage cp.async pipeline, 1 __syncthreads per 32-wide K-chunk.
// ---------------------------------------------------------------------------
template<int MODE>
__global__ void __launch_bounds__(256, 1) k_gemm(const float* __restrict__ bias,
                                                 float* __restrict__ outf) {
    extern __shared__ __align__(128) char sm[];
    const uint32_t smb = smem_u32(sm);
    const int t = threadIdx.x;
    const int b = blockIdx.z;

    int bx, by;
    if (MODE == 1) {
        int id = blockIdx.x;
        int byy = (int)((sqrtf(8.f * id + 1.f) - 1.f) * 0.5f);
        while ((byy + 1) * (byy + 2) / 2 <= id) ++byy;
        while (byy * (byy + 1) / 2 > id) --byy;
        by = byy; bx = id - byy * (byy + 1) / 2;   // bx <= by
    } else {
        bx = blockIdx.x; by = blockIdx.y;
    }

    constexpr int KTOT = (MODE == 2) ? N_ : C_;
    constexpr int KCH  = KTOT / 32;
    constexpr uint32_t STRIDE = (MODE == 2) ? 24576u : 32768u;

    const uint16_t *ah, *al, *bh, *bl;
    size_t a_rs, b_rs;
    if (MODE == 0) {
        size_t ao = (size_t)b * N_ * C_ + (size_t)bx * 128 * C_;
        ah = (const uint16_t*)g_xh + ao; al = (const uint16_t*)g_xl + ao; a_rs = C_;
        size_t bo = (size_t)by * 128 * C_;
        bh = (const uint16_t*)g_wh + bo; bl = (const uint16_t*)g_wl + bo; b_rs = C_;
    } else if (MODE == 1) {
        size_t ao = (size_t)b * N_ * C_ + (size_t)bx * 128 * C_;
        size_t bo = (size_t)b * N_ * C_ + (size_t)by * 128 * C_;
        ah = (const uint16_t*)g_qh + ao; al = (const uint16_t*)g_ql + ao; a_rs = C_;
        bh = (const uint16_t*)g_qh + bo; bl = (const uint16_t*)g_ql + bo; b_rs = C_;
    } else {
        size_t ao = (size_t)b * N_ * N_ + (size_t)bx * 128 * N_;
        size_t bo = (size_t)b * C_ * N_ + (size_t)by * 128 * N_;
        ah = (const uint16_t*)g_ph + ao; al = (const uint16_t*)g_pl + ao; a_rs = N_;
        bh = (const uint16_t*)g_v  + bo; bl = nullptr;                    b_rs = N_;
    }

    const int wid = t >> 5, lane = t & 31;
    const int wm = wid >> 2, wn = wid & 3;         // 2 x 4 warps
    const int m0w = wm * 64, n0w = wn * 32;

    float acc[4][4][4];
#pragma unroll
    for (int i = 0; i < 4; ++i)
#pragma unroll
        for (int j = 0; j < 4; ++j)
#pragma unroll
            for (int r = 0; r < 4; ++r) acc[i][j][r] = 0.f;

#define PREFETCH(kc_) do {                                                     \
        uint32_t st_ = smb + (uint32_t)((kc_) % 3) * STRIDE;                   \
        int k0_ = (kc_) * 32;                                                  \
        _Pragma("unroll")                                                      \
        for (int i_ = 0; i_ < 2; ++i_) {                                       \
            int lin_ = t + i_ * 256;                                           \
            int row_ = lin_ >> 2, ch_ = lin_ & 3;                              \
            uint32_t so_ = swz(row_, ch_);                                     \
            size_t ao_ = (size_t)row_ * a_rs + k0_ + ch_ * 8;                  \
            size_t bo_ = (size_t)row_ * b_rs + k0_ + ch_ * 8;                  \
            CP16(st_ + so_,          ah + ao_);                                \
            CP16(st_ + 8192 + so_,   al + ao_);                                \
            CP16(st_ + 16384 + so_,  bh + bo_);                                \
            if (MODE != 2) CP16(st_ + 24576 + so_, bl + bo_);                  \
        }                                                                      \
    } while (0)

    PREFETCH(0); CPCOMMIT();
    PREFETCH(1); CPCOMMIT();

    const int asub   = lane >> 3;
    const int arow   = (asub & 1) * 8 + (lane & 7);
    const int achoff = asub >> 1;
    const int bsub   = (lane >> 3) & 1;
    const int brow   = lane & 7;

#pragma unroll 1
    for (int kc = 0; kc < KCH; ++kc) {
        if (kc + 1 < KCH) CPWAIT1(); else CPWAIT0();
        __syncthreads();
        if (kc + 2 < KCH) { PREFETCH(kc + 2); CPCOMMIT(); }

        uint32_t st = smb + (uint32_t)(kc % 3) * STRIDE;
#pragma unroll
        for (int ks = 0; ks < 2; ++ks) {
            uint32_t Ah[4][4], Al[4][4], Bh[4][2], Bl[4][2];
#pragma unroll
            for (int i = 0; i < 4; ++i) {
                int row = m0w + i * 16 + arow;
                uint32_t ad = st + swz(row, ks * 2 + achoff);
                LDSM_X4(Ah[i], ad);
                LDSM_X4(Al[i], ad + 8192);
            }
#pragma unroll
            for (int j = 0; j < 4; ++j) {
                int row = n0w + j * 8 + brow;
                uint32_t ad = st + 16384 + swz(row, ks * 2 + bsub);
                LDSM_X2(Bh[j], ad);
                if (MODE != 2) LDSM_X2(Bl[j], ad + 8192);
            }
            if (MODE != 2) {
#pragma unroll
                for (int i = 0; i < 4; ++i)
#pragma unroll
                    for (int j = 0; j < 4; ++j) {
                        MMAB(acc[i][j], Ah[i], Bh[j]);
                        MMAB(acc[i][j], Ah[i], Bl[j]);
                        MMAB(acc[i][j], Al[i], Bh[j]);
                    }
            } else {
#pragma unroll
                for (int i = 0; i < 4; ++i)
#pragma unroll
                    for (int j = 0; j < 4; ++j) {
                        MMAH(acc[i][j], Ah[i], Bh[j]);
                        MMAH(acc[i][j], Al[i], Bh[j]);
                    }
            }
        }
    }
#undef PREFETCH

    __syncthreads();   // stages dead; about to alias with Ds

    // ---- epilogue: regs -> smem D[128][129] -> transformed stores ----
    float* Ds = (float*)sm;
#pragma unroll
    for (int i = 0; i < 4; ++i) {
        int r0 = m0w + i * 16 + (lane >> 2);
#pragma unroll
        for (int j = 0; j < 4; ++j) {
            int c0 = n0w + j * 8 + (lane & 3) * 2;
            Ds[r0 * 129 + c0]           = acc[i][j][0];
            Ds[r0 * 129 + c0 + 1]       = acc[i][j][1];
            Ds[(r0 + 8) * 129 + c0]     = acc[i][j][2];
            Ds[(r0 + 8) * 129 + c0 + 1] = acc[i][j][3];
        }
    }
    __syncthreads();

    const int jj = t & 127, half = t >> 7;
    float bv = 0.f;
    if (MODE == 0) bv = bias[by * 128 + jj];

    // pass 1: column reads (D^T): output row = D column jj
#pragma unroll 1
    for (int rb = 0; rb < 8; ++rb) {
        int r0 = half * 64 + rb * 8;
        float v[8];
#pragma unroll
        for (int u = 0; u < 8; ++u) v[u] = Ds[(r0 + u) * 129 + jj];

        if (MODE == 2) {
            float4* dst = (float4*)(outf + (size_t)b * C_ * N_
                                    + (size_t)(by * 128 + jj) * N_ + bx * 128 + r0);
            dst[0] = make_float4(v[0], v[1], v[2], v[3]);
            dst[1] = make_float4(v[4], v[5], v[6], v[7]);
        } else if (MODE == 0) {
            __align__(16) __half hv[8];
#pragma unroll
            for (int u = 0; u < 8; ++u) hv[u] = __float2half_rn(v[u] + bv);
            size_t off = (size_t)b * C_ * N_ + (size_t)(by * 128 + jj) * N_ + bx * 128 + r0;
            *(uint4*)(g_v + off) = *(uint4*)hv;
        } else {
            __align__(16) __half hb8[8], lb8[8];
#pragma unroll
            for (int u = 0; u < 8; ++u) {
                float xv = fmaxf(v[u], 0.f); xv = xv * xv;
                split2h(xv, hb8[u], lb8[u]);
            }
            size_t off = (size_t)b * N_ * N_ + (size_t)(by * 128 + jj) * N_ + bx * 128 + r0;
            *(uint4*)(g_ph + off) = *(uint4*)hb8;
            *(uint4*)(g_pl + off) = *(uint4*)lb8;
        }
    }

    // pass 2 (MODE 1, off-diagonal): row reads -> mirror block P[n][m]
    if (MODE == 1 && bx != by) {
        const int rr = t & 127, jh = t >> 7;
#pragma unroll 1
        for (int cb = 0; cb < 8; ++cb) {
            int c0 = jh * 64 + cb * 8;
            __align__(16) __half hb8[8], lb8[8];
#pragma unroll
            for (int u = 0; u < 8; ++u) {
                float xv = fmaxf(Ds[rr * 129 + c0 + u], 0.f); xv = xv * xv;
                split2h(xv, hb8[u], lb8[u]);
            }
            size_t off = (size_t)b * N_ * N_
                       + (size_t)(bx * 128 + rr) * N_ + by * 128 + c0;
            *(uint4*)(g_ph + off) = *(uint4*)hb8;
            *(uint4*)(g_pl + off) = *(uint4*)lb8;
        }
    }
}

// ---------------------------------------------------------------------------
extern "C" void kernel_launch(void* const* d_in, const int* in_sizes, int n_in,
                              void* d_out, int out_size) {
    const float* x    = (const float*)d_in[0];
    const float* Wm   = (const float*)d_in[1];
    const float* bias = (const float*)d_in[2];
    float* out = (float*)d_out;

    const int SMEM_AB = 3 * 32768;   // 96KB (modes 0/1)
    const int SMEM_C  = 3 * 24576;   // 72KB (mode 2)
    cudaFuncSetAttribute(k_gemm<0>, cudaFuncAttributeMaxDynamicSharedMemorySize, SMEM_AB);
    cudaFuncSetAttribute(k_gemm<1>, cudaFuncAttributeMaxDynamicSharedMemorySize, SMEM_AB);
    cudaFuncSetAttribute(k_gemm<2>, cudaFuncAttributeMaxDynamicSharedMemorySize, SMEM_C);

    k_prep<<<B_ * (N_ / 32), 256>>>(x);
    k_splitW<<<C_ * C_ / 256, 256>>>(Wm);

    k_gemm<0><<<dim3(N_ / 128, C_ / 128, B_), 256, SMEM_AB>>>(bias, nullptr);

    int tri = (N_ / 128) * (N_ / 128 + 1) / 2;     // 528 triangular tiles
    k_gemm<1><<<dim3(tri, 1, B_), 256, SMEM_AB>>>(nullptr, nullptr);

    k_gemm<2><<<dim3(N_ / 128, C_ / 128, B_), 256, SMEM_C>>>(nullptr, out);
}

// round 7
// speedup vs baseline: 8.9780x; 2.2758x over previous
#include <cuda_runtime.h>
#include <cuda_fp16.h>
#include <cstdint>

#define B_ 4
#define C_ 256
#define N_ 4096

// ---------------- device scratch (all fp16) ----------------
__device__ __half g_qf[(size_t)B_*N_*C_];   // normalized x, [b][n][c]
__device__ __half g_xf[(size_t)B_*N_*C_];   // raw x transposed, [b][n][c]
__device__ __half g_wf[C_*C_];              // W, [o][c]
__device__ __half g_v [(size_t)B_*C_*N_];   // conv out, [b][c][m]
__device__ __half g_p [(size_t)B_*N_*N_];   // P = relu(sim)^2, [b][i][j]

// ---------------- helpers ----------------
__device__ __forceinline__ uint32_t smem_u32(const void* p) {
    uint32_t a;
    asm("{ .reg .u64 t; cvta.to.shared.u64 t, %1; cvt.u32.u64 %0, t; }" : "=r"(a) : "l"(p));
    return a;
}

#define CP16(dst, src) \
    asm volatile("cp.async.cg.shared.global [%0], [%1], 16;" :: "r"(dst), "l"(src))
#define CPCOMMIT() asm volatile("cp.async.commit_group;" ::: "memory")
#define CPWAIT1()  asm volatile("cp.async.wait_group 1;" ::: "memory")
#define CPWAIT0()  asm volatile("cp.async.wait_group 0;" ::: "memory")

#define LDSM_X4(r, ad) \
    asm volatile("ldmatrix.sync.aligned.m8n8.x4.shared.b16 {%0,%1,%2,%3}, [%4];" \
        : "=r"((r)[0]), "=r"((r)[1]), "=r"((r)[2]), "=r"((r)[3]) : "r"(ad))
#define LDSM_X2(r, ad) \
    asm volatile("ldmatrix.sync.aligned.m8n8.x2.shared.b16 {%0,%1}, [%2];" \
        : "=r"((r)[0]), "=r"((r)[1]) : "r"(ad))

#define MMAH(d, a, bb) \
    asm volatile("mma.sync.aligned.m16n8k16.row.col.f32.f16.f16.f32 " \
        "{%0,%1,%2,%3}, {%4,%5,%6,%7}, {%8,%9}, {%0,%1,%2,%3};" \
        : "+f"((d)[0]), "+f"((d)[1]), "+f"((d)[2]), "+f"((d)[3]) \
        : "r"((a)[0]), "r"((a)[1]), "r"((a)[2]), "r"((a)[3]), "r"((bb)[0]), "r"((bb)[1]))

// swizzled 16B-chunk offset inside a [128 rows x 32 cols fp16] tile (64B rows)
__device__ __forceinline__ uint32_t swz(int row, int ch) {
    return (uint32_t)((row * 4 + (ch ^ ((row >> 1) & 3))) * 16);
}

// ---------------------------------------------------------------------------
// prep: per-pixel channel L2 norm; emit fp16(raw x) and fp16(normed x) [b][n][c]
// ---------------------------------------------------------------------------
__global__ __launch_bounds__(256) void k_prep(const float* __restrict__ x) {
    __shared__ float tile[C_ * 33];
    __shared__ float red[8 * 32];
    __shared__ float rn[32];

    int b  = blockIdx.x >> 7;
    int n0 = (blockIdx.x & 127) * 32;
    int t  = threadIdx.x;
    int nl = t & 31;
    int cg = t >> 5;

    const float* xb = x + (size_t)b * C_ * N_;
#pragma unroll 8
    for (int p = 0; p < 32; ++p) {
        int c = cg + p * 8;
        tile[c * 33 + nl] = xb[(size_t)c * N_ + n0 + nl];
    }
    __syncthreads();

    float ss = 0.f;
#pragma unroll 8
    for (int c = cg; c < C_; c += 8) { float v = tile[c * 33 + nl]; ss += v * v; }
    red[cg * 32 + nl] = ss;
    __syncthreads();
    if (t < 32) {
        float s = 0.f;
#pragma unroll
        for (int g = 0; g < 8; ++g) s += red[g * 32 + t];
        rn[t] = 1.f / fmaxf(sqrtf(s), 1e-8f);
    }
    __syncthreads();

#pragma unroll 8
    for (int n = 0; n < 32; ++n) {
        size_t idx = (size_t)(b * N_ + n0 + n) * C_ + t;
        float xv = tile[t * 33 + n];
        g_xf[idx] = __float2half_rn(xv);
        g_qf[idx] = __float2half_rn(xv * rn[n]);
    }
}

__global__ __launch_bounds__(256) void k_prepW(const float* __restrict__ W) {
    int i = blockIdx.x * 256 + threadIdx.x;
    g_wf[i] = __float2half_rn(W[i]);
}

// ---------------------------------------------------------------------------
// fp16 HMMA GEMM: D[128 x 128] = A[128,K] * B[128,K]^T, fp32 accum, 1 MMA/frag
// MODE 0: conv  A=x(m)  B=W(c)   +bias       -> g_v[c][m] fp16 (transposed)
// MODE 1: sim   A=q(n)  B=q(m)   relu^2      -> g_p[m][n] + mirror g_p[n][m]
//               (triangular grid over bx<=by)
// MODE 2: out   A=P(n)  B=v(c)               -> out[c][n] fp32 (transposed)
// 3-stage cp.async pipeline (16KB/stage), 2 CTAs/SM, half-pass epilogue.
// ---------------------------------------------------------------------------
template<int MODE>
__global__ void __launch_bounds__(256, 2) k1(const float* __restrict__ bias,
                                             float* __restrict__ outf) {
    extern __shared__ __align__(128) char sm[];
    const uint32_t smb = smem_u32(sm);
    const int t = threadIdx.x;
    const int b = blockIdx.z;

    int bx, by;
    if (MODE == 1) {
        int id = blockIdx.x;
        int byy = (int)((sqrtf(8.f * id + 1.f) - 1.f) * 0.5f);
        while ((byy + 1) * (byy + 2) / 2 <= id) ++byy;
        while (byy * (byy + 1) / 2 > id) --byy;
        by = byy; bx = id - byy * (byy + 1) / 2;   // bx <= by
    } else {
        bx = blockIdx.x; by = blockIdx.y;
    }

    constexpr int KTOT = (MODE == 2) ? N_ : C_;
    constexpr int KCH  = KTOT / 32;

    const __half *af, *bf;
    size_t a_rs, b_rs;
    if (MODE == 0) {
        af = g_xf + (size_t)b * N_ * C_ + (size_t)bx * 128 * C_; a_rs = C_;
        bf = g_wf + (size_t)by * 128 * C_;                       b_rs = C_;
    } else if (MODE == 1) {
        af = g_qf + (size_t)b * N_ * C_ + (size_t)bx * 128 * C_; a_rs = C_;
        bf = g_qf + (size_t)b * N_ * C_ + (size_t)by * 128 * C_; b_rs = C_;
    } else {
        af = g_p + (size_t)b * N_ * N_ + (size_t)bx * 128 * N_;  a_rs = N_;
        bf = g_v + (size_t)b * C_ * N_ + (size_t)by * 128 * N_;  b_rs = N_;
    }

    const int wid = t >> 5, lane = t & 31;
    const int wm = wid >> 2, wn = wid & 3;         // 2 x 4 warps
    const int m0w = wm * 64, n0w = wn * 32;

    float acc[4][4][4];
#pragma unroll
    for (int i = 0; i < 4; ++i)
#pragma unroll
        for (int j = 0; j < 4; ++j)
#pragma unroll
            for (int r = 0; r < 4; ++r) acc[i][j][r] = 0.f;

#define PREFETCH(kc_) do {                                                     \
        uint32_t st_ = smb + (uint32_t)((kc_) % 3) * 16384u;                   \
        int k0_ = (kc_) * 32;                                                  \
        _Pragma("unroll")                                                      \
        for (int i_ = 0; i_ < 2; ++i_) {                                       \
            int lin_ = t + i_ * 256;                                           \
            int row_ = lin_ >> 2, ch_ = lin_ & 3;                              \
            uint32_t so_ = swz(row_, ch_);                                     \
            CP16(st_ + so_,        af + (size_t)row_ * a_rs + k0_ + ch_ * 8);  \
            CP16(st_ + 8192 + so_, bf + (size_t)row_ * b_rs + k0_ + ch_ * 8);  \
        }                                                                      \
    } while (0)

    PREFETCH(0); CPCOMMIT();
    PREFETCH(1); CPCOMMIT();

    const int asub   = lane >> 3;
    const int arow   = (asub & 1) * 8 + (lane & 7);
    const int achoff = asub >> 1;
    const int bsub   = (lane >> 3) & 1;
    const int brow   = lane & 7;

#pragma unroll 1
    for (int kc = 0; kc < KCH; ++kc) {
        if (kc + 1 < KCH) CPWAIT1(); else CPWAIT0();
        __syncthreads();
        if (kc + 2 < KCH) { PREFETCH(kc + 2); CPCOMMIT(); }

        uint32_t st = smb + (uint32_t)(kc % 3) * 16384u;
#pragma unroll
        for (int ks = 0; ks < 2; ++ks) {
            uint32_t Ah[4][4], Bh[4][2];
#pragma unroll
            for (int i = 0; i < 4; ++i) {
                int row = m0w + i * 16 + arow;
                LDSM_X4(Ah[i], st + swz(row, ks * 2 + achoff));
            }
#pragma unroll
            for (int j = 0; j < 4; ++j) {
                int row = n0w + j * 8 + brow;
                LDSM_X2(Bh[j], st + 8192 + swz(row, ks * 2 + bsub));
            }
#pragma unroll
            for (int i = 0; i < 4; ++i)
#pragma unroll
                for (int j = 0; j < 4; ++j)
                    MMAH(acc[i][j], Ah[i], Bh[j]);
        }
    }
#undef PREFETCH

    // ---- epilogue: two half-passes (64 rows each) through Ds[64][129] ----
    float* Ds = (float*)sm;     // 64*129*4 = 33024 B  (< 48KB stages, now dead)
    const int jj = t & 127, seg = t >> 7;
    float bv = 0.f;
    if (MODE == 0) bv = bias[by * 128 + jj];

#pragma unroll 1
    for (int h = 0; h < 2; ++h) {
        __syncthreads();        // stages dead (h=0) / previous half consumed (h=1)
        if (wm == h) {
#pragma unroll
            for (int i = 0; i < 4; ++i) {
                int lr0 = i * 16 + (lane >> 2);
#pragma unroll
                for (int j = 0; j < 4; ++j) {
                    int c0 = n0w + j * 8 + (lane & 3) * 2;
                    Ds[lr0 * 129 + c0]           = acc[i][j][0];
                    Ds[lr0 * 129 + c0 + 1]       = acc[i][j][1];
                    Ds[(lr0 + 8) * 129 + c0]     = acc[i][j][2];
                    Ds[(lr0 + 8) * 129 + c0 + 1] = acc[i][j][3];
                }
            }
        }
        __syncthreads();

        // transposed consumption: output row = D column jj, cols = D rows
#pragma unroll 1
        for (int rb = 0; rb < 4; ++rb) {
            int lr0 = seg * 32 + rb * 8;
            float v[8];
#pragma unroll
            for (int u = 0; u < 8; ++u) v[u] = Ds[(lr0 + u) * 129 + jj];
            int gcol = bx * 128 + h * 64 + lr0;

            if (MODE == 2) {
                float4* dst = (float4*)(outf + (size_t)b * C_ * N_
                                        + (size_t)(by * 128 + jj) * N_ + gcol);
                dst[0] = make_float4(v[0], v[1], v[2], v[3]);
                dst[1] = make_float4(v[4], v[5], v[6], v[7]);
            } else if (MODE == 0) {
                __align__(16) __half hv[8];
#pragma unroll
                for (int u = 0; u < 8; ++u) hv[u] = __float2half_rn(v[u] + bv);
                size_t off = (size_t)b * C_ * N_ + (size_t)(by * 128 + jj) * N_ + gcol;
                *(uint4*)(g_v + off) = *(uint4*)hv;
            } else {
                __align__(16) __half hv[8];
#pragma unroll
                for (int u = 0; u < 8; ++u) {
                    float xv = fmaxf(v[u], 0.f);
                    hv[u] = __float2half_rn(xv * xv);
                }
                size_t off = (size_t)b * N_ * N_ + (size_t)(by * 128 + jj) * N_ + gcol;
                *(uint4*)(g_p + off) = *(uint4*)hv;
            }
        }

        // mirror store (sim, off-diagonal): P[bx*128+r][by*128+c] = D[r][c]
        if (MODE == 1 && bx != by) {
            const int lr = t & 63, cseg = t >> 6;
#pragma unroll 1
            for (int cb = 0; cb < 4; ++cb) {
                int c0 = cseg * 32 + cb * 8;
                __align__(16) __half hv[8];
#pragma unroll
                for (int u = 0; u < 8; ++u) {
                    float xv = fmaxf(Ds[lr * 129 + c0 + u], 0.f);
                    hv[u] = __float2half_rn(xv * xv);
                }
                size_t off = (size_t)b * N_ * N_
                           + (size_t)(bx * 128 + h * 64 + lr) * N_ + by * 128 + c0;
                *(uint4*)(g_p + off) = *(uint4*)hv;
            }
        }
    }
}

// ---------------------------------------------------------------------------
extern "C" void kernel_launch(void* const* d_in, const int* in_sizes, int n_in,
                              void* d_out, int out_size) {
    const float* x    = (const float*)d_in[0];
    const float* Wm   = (const float*)d_in[1];
    const float* bias = (const float*)d_in[2];
    float* out = (float*)d_out;

    const int SMEM = 3 * 16384;   // 48KB -> 2 CTAs/SM
    cudaFuncSetAttribute(k1<0>, cudaFuncAttributeMaxDynamicSharedMemorySize, SMEM);
    cudaFuncSetAttribute(k1<1>, cudaFuncAttributeMaxDynamicSharedMemorySize, SMEM);
    cudaFuncSetAttribute(k1<2>, cudaFuncAttributeMaxDynamicSharedMemorySize, SMEM);

    k_prep<<<B_ * (N_ / 32), 256>>>(x);
    k_prepW<<<C_ * C_ / 256, 256>>>(Wm);

    k1<0><<<dim3(N_ / 128, C_ / 128, B_), 256, SMEM>>>(bias, nullptr);

    int tri = (N_ / 128) * (N_ / 128 + 1) / 2;     // 528 triangular tiles
    k1<1><<<dim3(tri, 1, B_), 256, SMEM>>>(nullptr, nullptr);

    k1<2><<<dim3(N_ / 128, C_ / 128, B_), 256, SMEM>>>(nullptr, out);
}